// round 12
// baseline (speedup 1.0000x reference)
#include <cuda_runtime.h>
#include <cuda_bf16.h>

#define QN      400
#define PN      200000
#define NLAB    100
#define KS      8
#define THREADS 128
#define CHUNK   (PN / KS)                 // 25000 (divisible by 8)
#define NCOPY   32                        // bin copies per CTA (shared by 4 warps)
#define CVT_BLOCKS ((PN / 4 + 255) / 256) // 196

// ---------------- device scratch (no allocation allowed) ----------------
__device__ unsigned char g_lab8[PN];
__device__ int   g_blockhist[CVT_BLOCKS * NLAB];
__device__ float g_partial[KS * QN * NLAB * 2];   // [r][q][lab][{d,s}]
__device__ float g_totals[KS * QN * 2];           // [r][q][{f0tot, ptot}]

// ---------------- kernel 0: narrow labels to u8 + per-block histogram ----------------
__global__ void convert_labels(const int* __restrict__ labels) {
    __shared__ int hist[NLAB];
    const int tid = threadIdx.x;
    for (int i = tid; i < NLAB; i += 256) hist[i] = 0;
    __syncthreads();

    int i = blockIdx.x * blockDim.x + tid;
    int base = i * 4;
    if (base < PN) {
        int4 l = *(const int4*)(labels + base);
        uchar4 u;
        u.x = (unsigned char)l.x; u.y = (unsigned char)l.y;
        u.z = (unsigned char)l.z; u.w = (unsigned char)l.w;
        *(uchar4*)(g_lab8 + base) = u;
        atomicAdd(&hist[l.x], 1); atomicAdd(&hist[l.y], 1);
        atomicAdd(&hist[l.z], 1); atomicAdd(&hist[l.w], 1);
    }
    __syncthreads();
    for (int j = tid; j < NLAB; j += 256)
        g_blockhist[blockIdx.x * NLAB + j] = hist[j];
}

// ---- branch-free transform: 3 MUFU, no selects. Safe for |x| < 80. ----
__device__ __forceinline__ void xform(float x, float& d, float& p, float& f0) {
    float t, lg;
    asm("ex2.approx.f32 %0, %1;" : "=f"(t) : "f"(x * -1.4426950408889634f)); // e^-x
    float opt = 1.0f + t;
    asm("rcp.approx.f32 %0, %1;" : "=f"(p)  : "f"(opt));   // p = sigmoid(x)
    asm("lg2.approx.f32 %0, %1;" : "=f"(lg) : "f"(opt));
    float logp = lg * -0.69314718055994531f;               // log sigmoid(x)
    float l1mp = logp - x;                                 // log sigmoid(-x)
    float omp  = t * p;                                    // 1 - p, exact identity
    f0 = (p * p) * (l1mp * -0.75f);
    float f1 = (omp * omp) * (logp * -0.25f);
    d = f1 - f0;
}

// ---- fused per-element: transform + fire-and-forget bf16x2 shared reduction ----
__device__ __forceinline__ void elem(float x, unsigned lw, int i,
                                     unsigned sb_lane_addr, float& accf0) {
    int l = (int)((lw >> (8 * i)) & 0xffu);
    unsigned addr = sb_lane_addr + (unsigned)l * (NCOPY * 4);  // bins[l][lane]
    float d, p, f0;
    xform(x, d, p, f0);
    accf0 += f0;
    __nv_bfloat162 v = __floats2bfloat162_rn(d, p);            // .x=d, .y=p
    asm volatile("red.shared.add.noftz.bf16x2 [%0], %1;"
                 :: "r"(addr), "r"(*(unsigned*)&v) : "memory");
}

// ---------------- kernel 1: main segmented reduction (8 CTAs/SM, RED bins) ----------------
__global__ __launch_bounds__(THREADS, 8)
void main_kernel(const float* __restrict__ pred) {
    __shared__ __nv_bfloat162 sb[NLAB * NCOPY];   // 12.8 KB, bank = copy index
    const int tid = threadIdx.x;
    const int q = blockIdx.x;
    const int r = blockIdx.y;

    uint4* z4 = (uint4*)sb;
    for (int i = tid; i < (NLAB * NCOPY) / 4; i += THREADS)
        z4[i] = make_uint4(0u, 0u, 0u, 0u);
    __syncthreads();

    const float* row = pred + (size_t)q * PN + (size_t)r * CHUNK;
    const unsigned char* lab = g_lab8 + r * CHUNK;
    const unsigned sb_lane_addr =
        (unsigned)__cvta_generic_to_shared(sb) + (unsigned)(tid & (NCOPY - 1)) * 4u;

    float accf0 = 0.f;
    const int S = THREADS * 8;               // 1024

    // ---- prefetch first 8-element group (2x LDG.128 pred + 1x LDG.64 labels) ----
    int idx = tid * 8;
    float4 A0, A1; uint2 LW;
    if (idx < CHUNK) {
        A0 = __ldcs((const float4*)(row + idx));
        A1 = __ldcs((const float4*)(row + idx + 4));
        LW = *(const uint2*)(lab + idx);
    }

    while (idx < CHUNK) {
        int nidx = idx + S;
        float4 B0, B1; uint2 NLW;
        if (nidx < CHUNK) {                  // next group's loads in flight during body
            B0 = __ldcs((const float4*)(row + nidx));
            B1 = __ldcs((const float4*)(row + nidx + 4));
            NLW = *(const uint2*)(lab + nidx);
        }

        elem(A0.x, LW.x, 0, sb_lane_addr, accf0);
        elem(A0.y, LW.x, 1, sb_lane_addr, accf0);
        elem(A0.z, LW.x, 2, sb_lane_addr, accf0);
        elem(A0.w, LW.x, 3, sb_lane_addr, accf0);
        elem(A1.x, LW.y, 0, sb_lane_addr, accf0);
        elem(A1.y, LW.y, 1, sb_lane_addr, accf0);
        elem(A1.z, LW.y, 2, sb_lane_addr, accf0);
        elem(A1.w, LW.y, 3, sb_lane_addr, accf0);

        A0 = B0; A1 = B1; LW = NLW;
        idx = nidx;
    }
    __syncthreads();

    // reduce 32 copies per label -> deterministic partial buffer (exact f32)
    float ss = 0.f;
    if (tid < NLAB) {
        float ds = 0.f;
        #pragma unroll 8
        for (int i = 0; i < NCOPY; i++) {
            float2 v = __bfloat1622float2(sb[tid * NCOPY + ((i + tid) & (NCOPY - 1))]);
            ds += v.x; ss += v.y;
        }
        int o = ((r * QN + q) * NLAB + tid) * 2;
        g_partial[o]     = ds;
        g_partial[o + 1] = ss;
    }
    __syncthreads();

    // total p = sum of ss over all labels (every point has exactly one label)
    float* sred = (float*)sb;
    sred[tid] = ss;
    __syncthreads();
    #pragma unroll
    for (int s = THREADS / 2; s >= 32; s >>= 1) {
        if (tid < s) sred[tid] += sred[tid + s];
        __syncthreads();
    }
    if (tid < 32) {
        float v = sred[tid];
        #pragma unroll
        for (int off = 16; off; off >>= 1) v += __shfl_down_sync(0xffffffffu, v, off);
        if (tid == 0) g_totals[(r * QN + q) * 2 + 1] = v;
    }

    // row total f0 (exact f32 path)
    #pragma unroll
    for (int off = 16; off; off >>= 1)
        accf0 += __shfl_down_sync(0xffffffffu, accf0, off);
    __shared__ float ws[4];
    if ((tid & 31) == 0) ws[tid >> 5] = accf0;
    __syncthreads();
    if (tid == 0) {
        float f = ws[0] + ws[1] + ws[2] + ws[3];
        g_totals[(r * QN + q) * 2 + 0] = f;
    }
}

// ---------------- kernel 2: counts + cost assembly ----------------
__global__ void finalize(float* __restrict__ out) {
    const int j = blockIdx.x;           // label 0..99
    const int tid = threadIdx.x;        // 256 threads

    int c = 0;
    for (int b = tid; b < CVT_BLOCKS; b += 256)
        c += g_blockhist[b * NLAB + j];
    #pragma unroll
    for (int off = 16; off; off >>= 1) c += __shfl_down_sync(0xffffffffu, c, off);
    __shared__ int cs[8];
    if ((tid & 31) == 0) cs[tid >> 5] = c;
    __syncthreads();
    int cnt = 0;
    #pragma unroll
    for (int w = 0; w < 8; w++) cnt += cs[w];
    float fc = (float)cnt;

    for (int q = tid; q < QN; q += 256) {
        float dsum = 0.f, ssum = 0.f, f0t = 0.f, pt = 0.f;
        #pragma unroll
        for (int r = 0; r < KS; r++) {
            int bi = ((r * QN + q) * NLAB + j) * 2;
            dsum += g_partial[bi];
            ssum += g_partial[bi + 1];
            f0t  += g_totals[(r * QN + q) * 2 + 0];
            pt   += g_totals[(r * QN + q) * 2 + 1];
        }
        float cmask = (dsum + f0t) * (1.0f / (float)PN);
        float dice  = 1.0f - (2.0f * ssum + 1.0f) / (pt + fc + 1.0f);
        out[q * NLAB + j] = cmask + dice;
    }
}

// ---------------- launch ----------------
extern "C" void kernel_launch(void* const* d_in, const int* in_sizes, int n_in,
                              void* d_out, int out_size) {
    const float* pred  = (const float*)d_in[0];
    const int* labels  = (const int*)d_in[1];
    float* out = (float*)d_out;

    convert_labels<<<CVT_BLOCKS, 256>>>(labels);
    dim3 grid(QN, KS);
    main_kernel<<<grid, THREADS>>>(pred);
    finalize<<<NLAB, 256>>>(out);
}